// round 9
// baseline (speedup 1.0000x reference)
#include <cuda_runtime.h>
#include <cstdint>

#define BB 512
#define NN 4096
#define RR 4097
#define TPB 512
#define EPT 8

#define CONTENT_PAD 1024
#define CONTENT_EOS 1025

// packed word: val in bits [0,11), pos in bits [11,23)
#define PACK(v, p)   ((v) | ((p) << 11))
#define UNPACK_V(w)  ((w) & 0x7FF)
#define UNPACK_P(w)  ((w) >> 11)

__global__ __launch_bounds__(TPB) void triple_grain_kernel(
    const int* __restrict__ in0,
    const int* __restrict__ in1,
    float* __restrict__ out)
{
    const int b    = blockIdx.x;
    const int tid  = threadIdx.x;
    const int lane = tid & 31;
    const int wid  = tid >> 5;

    __shared__ int buf[NN];                        // 16 KB staging: [s0 | s1 | s2]
    __shared__ unsigned long long warp_sums[16];

    const int* row0 = in0 + (long long)b * NN;
    const int* row1 = in1 + (long long)b * NN;

    // ---- load 8 contiguous elements from each candidate input ----
    int4 a0 = ((const int4*)row0)[tid * 2 + 0];
    int4 a1 = ((const int4*)row0)[tid * 2 + 1];
    int4 c0 = ((const int4*)row1)[tid * 2 + 0];
    int4 c1 = ((const int4*)row1)[tid * 2 + 1];
    int as[EPT] = {a0.x, a0.y, a0.z, a0.w, a1.x, a1.y, a1.z, a1.w};
    int cs[EPT] = {c0.x, c0.y, c0.z, c0.w, c1.x, c1.y, c1.z, c1.w};

    // ---- identify which input is the grain array (values all in {0,1,2}) ----
    int a_ge3 = 0;
#pragma unroll
    for (int i = 0; i < EPT; i++) a_ge3 |= ((unsigned)as[i] >= 3u);
    const int in0_is_indices = __syncthreads_or(a_ge3);

    int gs[EPT], vs[EPT];
#pragma unroll
    for (int i = 0; i < EPT; i++) {
        gs[i] = in0_is_indices ? cs[i] : as[i];
        vs[i] = in0_is_indices ? as[i] : cs[i];
    }

    // pack per-thread counts: 21-bit fields
    unsigned long long cnt = 0ULL;
#pragma unroll
    for (int i = 0; i < EPT; i++) cnt += 1ULL << (gs[i] * 21);

    // ---- block inclusive scan of packed counters ----
    unsigned long long inc = cnt;
#pragma unroll
    for (int d = 1; d < 32; d <<= 1) {
        unsigned long long v = __shfl_up_sync(0xffffffffu, inc, d);
        if (lane >= d) inc += v;
    }
    if (lane == 31) warp_sums[wid] = inc;
    __syncthreads();
    if (wid == 0) {
        unsigned long long v = (lane < 16) ? warp_sums[lane] : 0ULL;
#pragma unroll
        for (int d = 1; d < 16; d <<= 1) {
            unsigned long long u = __shfl_up_sync(0xffffffffu, v, d);
            if (lane >= d) v += u;
        }
        if (lane < 16) warp_sums[lane] = v;
    }
    __syncthreads();

    unsigned long long excl  = inc - cnt + (wid > 0 ? warp_sums[wid - 1] : 0ULL);
    unsigned long long total = warp_sums[15];

    const int t0 = (int)( total        & 0x1FFFFFULL);
    const int t1 = (int)((total >> 21) & 0x1FFFFFULL);
    const int t2 = (int)((total >> 42) & 0x1FFFFFULL);

    int off[3];
    off[0] =           (int)( excl        & 0x1FFFFFULL);
    off[1] = t0 +      (int)((excl >> 21) & 0x1FFFFFULL);
    off[2] = t0 + t1 + (int)((excl >> 42) & 0x1FFFFFULL);

    // ---- stable scatter of packed (val|pos) into smem ----
    const int base_pos = tid * EPT;
#pragma unroll
    for (int i = 0; i < EPT; i++) {
        int g = gs[i];
        buf[off[g]] = PACK(vs[i], base_pos + i);
        off[g]++;
    }
    __syncthreads();

    // ---- vectorized float32 output of 9 rows ----
    const int cnts[3]   = {t0, t1, t2};
    const int bases[3]  = {0, t0, t0 + t1};
    const int posEOS[3] = {129, 257, 1025};
    const int posPAD[3] = {128, 256, 1024};

    float* out_c = out;                                  // contents:  3 x [512, RR]
    float* out_p = out + (long long)3 * BB * RR;         // positions: 3 x [512, RR]
    float* out_s = out + (long long)6 * BB * RR;         // segments:  3 x [512, RR]

    // row base offset (g*512+b)*4097 mod 4 == b mod 4, same for all 9 rows
    const int pre   = (4 - (b & 3)) & 3;                 // scalars before aligned region
    const int nvec  = (RR - pre) >> 2;                   // float4 chunks
    const int tailn = (RR - pre) & 3;                    // scalars after

#pragma unroll
    for (int g = 0; g < 3; g++) {
        const int cg = cnts[g];
        const int bg = bases[g];
        float* oc = out_c + ((long long)g * BB + b) * RR;
        float* op = out_p + ((long long)g * BB + b) * RR;
        float* os = out_s + ((long long)g * BB + b) * RR;
        const int pe = posEOS[g], pp = posPAD[g];
        const float fg = (float)g;
        const float4 s4 = make_float4(fg, fg, fg, fg);
        const float4 cpad4 = make_float4(CONTENT_PAD, CONTENT_PAD, CONTENT_PAD, CONTENT_PAD);
        const float4 ppad4 = make_float4((float)pp, (float)pp, (float)pp, (float)pp);

        // scalar prologue + tail (<= 6 elements total)
        const int nscal = pre + tailn;
        if (tid < nscal) {
            int j = (tid < pre) ? tid : (pre + 4 * nvec + (tid - pre));
            int cv, pv;
            if (j < cg)      { int w = buf[bg + j]; cv = UNPACK_V(w); pv = UNPACK_P(w); }
            else if (j == cg){ cv = CONTENT_EOS; pv = pe; }
            else             { cv = CONTENT_PAD; pv = pp; }
            oc[j] = (float)cv;
            op[j] = (float)pv;
            os[j] = fg;
        }

        // vector interior
        for (int v = tid; v < nvec; v += TPB) {
            const int j0 = pre + 4 * v;
            float4 c4, p4;
            if (j0 + 3 < cg) {
                int w0 = buf[bg + j0 + 0];
                int w1 = buf[bg + j0 + 1];
                int w2 = buf[bg + j0 + 2];
                int w3 = buf[bg + j0 + 3];
                c4 = make_float4((float)UNPACK_V(w0), (float)UNPACK_V(w1),
                                 (float)UNPACK_V(w2), (float)UNPACK_V(w3));
                p4 = make_float4((float)UNPACK_P(w0), (float)UNPACK_P(w1),
                                 (float)UNPACK_P(w2), (float)UNPACK_P(w3));
            } else if (j0 > cg) {
                c4 = cpad4;
                p4 = ppad4;
            } else {
                float cc[4], ppv[4];
#pragma unroll
                for (int k = 0; k < 4; k++) {
                    int j = j0 + k;
                    int cv, pv;
                    if (j < cg)      { int w = buf[bg + j]; cv = UNPACK_V(w); pv = UNPACK_P(w); }
                    else if (j == cg){ cv = CONTENT_EOS; pv = pe; }
                    else             { cv = CONTENT_PAD; pv = pp; }
                    cc[k] = (float)cv; ppv[k] = (float)pv;
                }
                c4 = make_float4(cc[0], cc[1], cc[2], cc[3]);
                p4 = make_float4(ppv[0], ppv[1], ppv[2], ppv[3]);
            }
            *(float4*)(oc + j0) = c4;
            *(float4*)(op + j0) = p4;
            *(float4*)(os + j0) = s4;
        }
    }
}

extern "C" void kernel_launch(void* const* d_in, const int* in_sizes, int n_in,
                              void* d_out, int out_size)
{
    const int* in0 = (const int*)d_in[0];
    const int* in1 = (const int*)d_in[1];
    float* out = (float*)d_out;
    triple_grain_kernel<<<BB, TPB>>>(in0, in1, out);
}

// round 10
// speedup vs baseline: 1.0683x; 1.0683x over previous
#include <cuda_runtime.h>
#include <cstdint>

#define BB 512
#define NN 4096
#define RR 4097
#define TPB 512
#define EPT 8

#define CONTENT_PAD 1024
#define CONTENT_EOS 1025

// packed word: val in bits [0,11), pos in bits [11,23)
#define PACK(v, p)   ((v) | ((p) << 11))
#define UNPACK_V(w)  ((w) & 0x7FF)
#define UNPACK_P(w)  ((w) >> 11)

__constant__ int c_posEOS[3] = {129, 257, 1025};
__constant__ int c_posPAD[3] = {128, 256, 1024};

__global__ __launch_bounds__(TPB) void triple_grain_kernel(
    const int* __restrict__ in0,
    const int* __restrict__ in1,
    float* __restrict__ out)
{
    const int b    = blockIdx.x;
    const int g    = blockIdx.y;          // grain stream handled by this CTA
    const int tid  = threadIdx.x;
    const int lane = tid & 31;
    const int wid  = tid >> 5;

    __shared__ int buf[NN];               // 16 KB staging for this stream
    __shared__ int warp_sums[16];

    const int* row0 = in0 + (long long)b * NN;
    const int* row1 = in1 + (long long)b * NN;

    // ---- load 8 contiguous elements from each candidate input ----
    int4 a0 = ((const int4*)row0)[tid * 2 + 0];
    int4 a1 = ((const int4*)row0)[tid * 2 + 1];
    int4 c0 = ((const int4*)row1)[tid * 2 + 0];
    int4 c1 = ((const int4*)row1)[tid * 2 + 1];
    int as[EPT] = {a0.x, a0.y, a0.z, a0.w, a1.x, a1.y, a1.z, a1.w};
    int cs[EPT] = {c0.x, c0.y, c0.z, c0.w, c1.x, c1.y, c1.z, c1.w};

    // ---- identify which input is the grain array (values all in {0,1,2}) ----
    int a_ge3 = 0;
#pragma unroll
    for (int i = 0; i < EPT; i++) a_ge3 |= ((unsigned)as[i] >= 3u);
    const int in0_is_indices = __syncthreads_or(a_ge3);

    int flags[EPT], vs[EPT];
    int cnt = 0;
#pragma unroll
    for (int i = 0; i < EPT; i++) {
        int gv = in0_is_indices ? cs[i] : as[i];
        vs[i]  = in0_is_indices ? as[i] : cs[i];
        flags[i] = (gv == g);
        cnt += flags[i];
    }

    // ---- block inclusive scan of per-thread count (single counter) ----
    int inc = cnt;
#pragma unroll
    for (int d = 1; d < 32; d <<= 1) {
        int v = __shfl_up_sync(0xffffffffu, inc, d);
        if (lane >= d) inc += v;
    }
    if (lane == 31) warp_sums[wid] = inc;
    __syncthreads();
    if (wid == 0) {
        int v = (lane < 16) ? warp_sums[lane] : 0;
#pragma unroll
        for (int d = 1; d < 16; d <<= 1) {
            int u = __shfl_up_sync(0xffffffffu, v, d);
            if (lane >= d) v += u;
        }
        if (lane < 16) warp_sums[lane] = v;
    }
    __syncthreads();

    int off = inc - cnt + (wid > 0 ? warp_sums[wid - 1] : 0);
    const int cg = warp_sums[15];         // total selected in this stream

    // ---- stable scatter of packed (val|pos) into smem ----
    const int base_pos = tid * EPT;
#pragma unroll
    for (int i = 0; i < EPT; i++) {
        if (flags[i]) {
            buf[off] = PACK(vs[i], base_pos + i);
            off++;
        }
    }
    __syncthreads();

    // ---- vectorized float32 output of this CTA's 3 rows ----
    const int pe = c_posEOS[g], pp = c_posPAD[g];
    const float fg = (float)g;

    float* oc = out + ((long long)g       * BB + b) * RR;   // content
    float* op = out + ((long long)(3 + g) * BB + b) * RR;   // position
    float* os = out + ((long long)(6 + g) * BB + b) * RR;   // segment

    // row base offset mod 4 == b mod 4 (4097 ≡ 1 mod 4, 512 ≡ 0)
    const int pre   = (4 - (b & 3)) & 3;
    const int nvec  = (RR - pre) >> 2;
    const int tailn = (RR - pre) & 3;

    const float4 s4    = make_float4(fg, fg, fg, fg);
    const float4 cpad4 = make_float4(CONTENT_PAD, CONTENT_PAD, CONTENT_PAD, CONTENT_PAD);
    const float4 ppad4 = make_float4((float)pp, (float)pp, (float)pp, (float)pp);

    // scalar prologue + tail (<= 6 elements)
    const int nscal = pre + tailn;
    if (tid < nscal) {
        int j = (tid < pre) ? tid : (pre + 4 * nvec + (tid - pre));
        int cv, pv;
        if (j < cg)       { int w = buf[j]; cv = UNPACK_V(w); pv = UNPACK_P(w); }
        else if (j == cg) { cv = CONTENT_EOS; pv = pe; }
        else              { cv = CONTENT_PAD; pv = pp; }
        __stcs(oc + j, (float)cv);
        __stcs(op + j, (float)pv);
        __stcs(os + j, fg);
    }

    // vector interior: 1024 chunks / 512 threads = 2 per thread
    for (int v = tid; v < nvec; v += TPB) {
        const int j0 = pre + 4 * v;
        float4 c4, p4;
        if (j0 + 3 < cg) {
            int w0 = buf[j0 + 0];
            int w1 = buf[j0 + 1];
            int w2 = buf[j0 + 2];
            int w3 = buf[j0 + 3];
            c4 = make_float4((float)UNPACK_V(w0), (float)UNPACK_V(w1),
                             (float)UNPACK_V(w2), (float)UNPACK_V(w3));
            p4 = make_float4((float)UNPACK_P(w0), (float)UNPACK_P(w1),
                             (float)UNPACK_P(w2), (float)UNPACK_P(w3));
        } else if (j0 > cg) {
            c4 = cpad4;
            p4 = ppad4;
        } else {
            float cc[4], ppv[4];
#pragma unroll
            for (int k = 0; k < 4; k++) {
                int j = j0 + k;
                int cv, pv;
                if (j < cg)       { int w = buf[j]; cv = UNPACK_V(w); pv = UNPACK_P(w); }
                else if (j == cg) { cv = CONTENT_EOS; pv = pe; }
                else              { cv = CONTENT_PAD; pv = pp; }
                cc[k] = (float)cv; ppv[k] = (float)pv;
            }
            c4 = make_float4(cc[0], cc[1], cc[2], cc[3]);
            p4 = make_float4(ppv[0], ppv[1], ppv[2], ppv[3]);
        }
        __stcs((float4*)(oc + j0), c4);
        __stcs((float4*)(op + j0), p4);
        __stcs((float4*)(os + j0), s4);
    }
}

extern "C" void kernel_launch(void* const* d_in, const int* in_sizes, int n_in,
                              void* d_out, int out_size)
{
    const int* in0 = (const int*)d_in[0];
    const int* in1 = (const int*)d_in[1];
    float* out = (float*)d_out;
    dim3 grid(BB, 3);
    triple_grain_kernel<<<grid, TPB>>>(in0, in1, out);
}